// round 10
// baseline (speedup 1.0000x reference)
#include <cuda_runtime.h>

// Problem constants
#define Bn 32
#define Cc 3
#define Hd 384
#define Wd 640

// Tiling
#define TW 128      // output cols per block
#define TH 16       // output rows per block
#define PW 130      // padded cols (TW + 2)
#define PWs 132     // smem row stride (in float2)
#define PH 18       // padded rows (TH + 2)
#define RPT 8       // rows per thread (TH / 2)

__device__ __forceinline__ int reflect1(int i, int n) {
    // jnp.pad mode='reflect', pad=1: -1 -> 1, n -> n-2
    if (i < 0) i = -i;
    if (i >= n) i = 2 * n - 2 - i;
    return i;
}

__global__ __launch_bounds__(256, 4)
void recon_loss_kernel(const float* __restrict__ X,
                       const float* __restrict__ Y,
                       float* __restrict__ out) {
    // Interleaved (x, y) tile: LDS.64 halves LDS instruction count.
    __shared__ float2 s[PH][PWs];

    const int w0 = blockIdx.x * TW;
    const int h0 = blockIdx.y * TH;
    const int b  = blockIdx.z;
    const int tid = threadIdx.x;
    const int col = tid & (TW - 1);        // 0..127
    const int row_base = (tid >> 7) * RPT; // 0 or 8

    // ---- load geometry: computed ONCE, reused for all 3 channels ----
    // Main map: thread covers (i = i0 + 2k, j = jm) for k = 0..8.
    const int i0 = tid >> 7;                       // 0 or 1
    const int jm = tid & 127;                      // padded col 0..127
    const int gcm = reflect1(w0 - 1 + jm, Wd);     // reflected global col
    const int rb  = h0 - 1 + i0;                   // base padded-row -> global row
    // Tail: 36 threads cover padded cols 128,129 for all 18 rows.
    const bool tail = tid < 36;
    const int ti  = tid >> 1;                      // 0..17
    const int tj  = 128 + (tid & 1);
    const int tg  = reflect1(h0 - 1 + ti, Hd) * Wd + reflect1(w0 - 1 + tj, Wd);

    // 81*C1 == 9*C2 == 526.7025 (since C2 = 9*C1)
    const float KC  = 526.7025f;
    const float KC9 = 4740.3225f;   // 81*C2

    // Single merged accumulator: 0.425*sum(ns) + 0.15*sum(|dv|)
    float acc[RPT];
#pragma unroll
    for (int i = 0; i < RPT; i++) acc[i] = 0.0f;

    for (int c = 0; c < Cc; c++) {
        const float* __restrict__ xb = X + (size_t)(b * Cc + c) * (Hd * Wd);
        const float* __restrict__ yb = Y + (size_t)(b * Cc + c) * (Hd * Wd);

        __syncthreads();   // protect smem from readers of previous channel

        // Cooperative load of reflect-padded tile: fixed (i,j) map, no division.
#pragma unroll
        for (int k = 0; k < 9; k++) {
            int gr = reflect1(rb + 2 * k, Hd);
            int g  = gr * Wd + gcm;
            s[i0 + 2 * k][jm] = make_float2(xb[g], yb[g]);
        }
        if (tail) s[ti][tj] = make_float2(xb[tg], yb[tg]);
        __syncthreads();

        // Rolling horizontal row-sums (ring of 3):
        //   rs_x = sum x, rs_y = sum y, rs_q = sum (x^2 + y^2), rs_xy = sum x*y
        float rs_x[3], rs_y[3], rs_q[3], rs_xy[3], dv[3];

#pragma unroll
        for (int k = 0; k < 2; k++) {
            int pr = row_base + k;
            float2 v0 = s[pr][col], v1 = s[pr][col + 1], v2 = s[pr][col + 2];
            rs_x[k]  = v0.x + v1.x + v2.x;
            rs_y[k]  = v0.y + v1.y + v2.y;
            rs_q[k]  = v0.x * v0.x + v0.y * v0.y + v1.x * v1.x + v1.y * v1.y
                     + v2.x * v2.x + v2.y * v2.y;
            rs_xy[k] = v0.x * v0.y + v1.x * v1.y + v2.x * v2.y;
            dv[k]    = v1.x - v1.y;
        }

#pragma unroll
        for (int h = 0; h < RPT; h++) {
            const int kn = (h + 2) % 3;   // slot for the new (bottom) row
            const int km = (h + 1) % 3;   // slot holding the center row
            int pr = row_base + h + 2;
            float2 v0 = s[pr][col], v1 = s[pr][col + 1], v2 = s[pr][col + 2];
            rs_x[kn]  = v0.x + v1.x + v2.x;
            rs_y[kn]  = v0.y + v1.y + v2.y;
            rs_q[kn]  = v0.x * v0.x + v0.y * v0.y + v1.x * v1.x + v1.y * v1.y
                      + v2.x * v2.x + v2.y * v2.y;
            rs_xy[kn] = v0.x * v0.y + v1.x * v1.y + v2.x * v2.y;
            dv[kn]    = v1.x - v1.y;

            // Raw 3x3 window sums
            float Sx  = rs_x[0]  + rs_x[1]  + rs_x[2];
            float Sy  = rs_y[0]  + rs_y[1]  + rs_y[2];
            float Sq  = rs_q[0]  + rs_q[1]  + rs_q[2];   // Sxx + Syy
            float Sxy = rs_xy[0] + rs_xy[1] + rs_xy[2];

            // Scaled-through SSIM (exact rearrangement; uses C2 = 9*C1):
            //   P = 2*Sx*Sy + 81C1, Q = 18*Sxy - 2*Sx*Sy + 81C2
            //   R = Sx^2 + Sy^2 + 81C1, T = Sq - Sx - Sy + 9C2
            //   ns = 0.5 - (P*Q)/(R*T)/18
            float t = Sx * Sy;
            float P = fmaf(2.0f, t, KC);
            float Q = fmaf(18.0f, Sxy, fmaf(-2.0f, t, KC9));
            float R = fmaf(Sx, Sx, fmaf(Sy, Sy, KC));
            float T = Sq + (KC - (Sx + Sy));
            float ratio = __fdividef(P * Q, R * T);
            float ns = fmaf(ratio, -(1.0f / 18.0f), 0.5f);
            ns = fminf(fmaxf(ns, 0.0f), 1.0f);

            acc[h] = fmaf(0.425f, ns, fmaf(0.15f, fabsf(dv[km]), acc[h]));
        }
    }

    // Combine and write (coalesced per warp-row)
    float* __restrict__ ob = out + (size_t)b * Hd * Wd;
#pragma unroll
    for (int h = 0; h < RPT; h++) {
        int gr = h0 + row_base + h;
        ob[gr * Wd + w0 + col] = acc[h] * (1.0f / 3.0f);
    }
}

extern "C" void kernel_launch(void* const* d_in, const int* in_sizes, int n_in,
                              void* d_out, int out_size) {
    const float* X = (const float*)d_in[0];   // output
    const float* Y = (const float*)d_in[1];   // target
    float* O = (float*)d_out;

    dim3 grid(Wd / TW, Hd / TH, Bn);   // 5 x 24 x 32
    dim3 block(256);
    recon_loss_kernel<<<grid, block>>>(X, Y, O);
}

// round 13
// speedup vs baseline: 1.1534x; 1.1534x over previous
#include <cuda_runtime.h>

// Problem constants
#define Bn 32
#define Cc 3
#define Hd 384
#define Wd 640

// Tiling
#define TW 128      // output cols per block
#define TH 16       // output rows per block
#define PW 130      // padded cols (TW + 2)
#define PWs 132     // smem row stride (in float2)
#define PH 18       // padded rows (TH + 2)
#define RPT 8       // rows per thread (TH / 2)

__device__ __forceinline__ int reflect1(int i, int n) {
    // jnp.pad mode='reflect', pad=1: -1 -> 1, n -> n-2
    if (i < 0) i = -i;
    if (i >= n) i = 2 * n - 2 - i;
    return i;
}

__device__ __forceinline__ void cp4(unsigned dst, const float* src) {
    asm volatile("cp.async.ca.shared.global [%0], [%1], 4;\n"
                 :: "r"(dst), "l"(src));
}

__global__ __launch_bounds__(256, 3)
void recon_loss_kernel(const float* __restrict__ X,
                       const float* __restrict__ Y,
                       float* __restrict__ out) {
    // Ping-pong interleaved (x, y) tiles: LDS.64 reads, cp.async fills.
    __shared__ float2 s[2][PH][PWs];

    const int w0 = blockIdx.x * TW;
    const int h0 = blockIdx.y * TH;
    const int b  = blockIdx.z;
    const int tid = threadIdx.x;
    const int col = tid & (TW - 1);        // 0..127
    const int row_base = (tid >> 7) * RPT; // 0 or 8

    // ---- load geometry: computed ONCE, reused for all 3 channels ----
    const int i0 = tid >> 7;                       // 0 or 1
    const int jm = tid & 127;                      // padded col 0..127
    const int gcm = reflect1(w0 - 1 + jm, Wd);     // reflected global col
    const int rb  = h0 - 1 + i0;                   // base padded-row
    // Tail: 36 threads cover padded cols 128,129 for all 18 rows.
    const bool tail = tid < 36;
    const int ti  = tid >> 1;                      // 0..17
    const int tj  = 128 + (tid & 1);
    const int tg  = reflect1(h0 - 1 + ti, Hd) * Wd + reflect1(w0 - 1 + tj, Wd);

    const float KC  = 526.7025f;    // 81*C1 == 9*C2
    const float KC9 = 4740.3225f;   // 81*C2

    float acc[RPT];
#pragma unroll
    for (int i = 0; i < RPT; i++) acc[i] = 0.0f;

    // Async-load channel cc into buffer cc&1
    auto issue_loads = [&](int cc) {
        const float* __restrict__ xb = X + (size_t)(b * Cc + cc) * (Hd * Wd);
        const float* __restrict__ yb = Y + (size_t)(b * Cc + cc) * (Hd * Wd);
        float2 (*buf)[PWs] = s[cc & 1];
#pragma unroll
        for (int k = 0; k < 9; k++) {
            int gr = reflect1(rb + 2 * k, Hd);
            int g  = gr * Wd + gcm;
            unsigned dst = (unsigned)__cvta_generic_to_shared(&buf[i0 + 2 * k][jm]);
            cp4(dst,     xb + g);
            cp4(dst + 4, yb + g);
        }
        if (tail) {
            unsigned dst = (unsigned)__cvta_generic_to_shared(&buf[ti][tj]);
            cp4(dst,     xb + tg);
            cp4(dst + 4, yb + tg);
        }
        asm volatile("cp.async.commit_group;\n" ::: "memory");
    };

    issue_loads(0);

    for (int c = 0; c < Cc; c++) {
        // Retire the group filling buffer c; barrier makes it CTA-visible and
        // also guarantees everyone is done computing on buffer (c&1)^1 from
        // two channels ago before we overwrite it below.
        asm volatile("cp.async.wait_group 0;\n" ::: "memory");
        __syncthreads();
        if (c + 1 < Cc) issue_loads(c + 1);   // overlaps with compute below

        float2 (*buf)[PWs] = s[c & 1];

        // Rolling horizontal row-sums (ring of 3):
        //   rs_x = sum x, rs_y = sum y, rs_q = sum (x^2+y^2), rs_xy = sum x*y
        float rs_x[3], rs_y[3], rs_q[3], rs_xy[3], dv[3];

#pragma unroll
        for (int k = 0; k < 2; k++) {
            int pr = row_base + k;
            float2 v0 = buf[pr][col], v1 = buf[pr][col + 1], v2 = buf[pr][col + 2];
            rs_x[k]  = v0.x + v1.x + v2.x;
            rs_y[k]  = v0.y + v1.y + v2.y;
            rs_q[k]  = v0.x * v0.x + v0.y * v0.y + v1.x * v1.x + v1.y * v1.y
                     + v2.x * v2.x + v2.y * v2.y;
            rs_xy[k] = v0.x * v0.y + v1.x * v1.y + v2.x * v2.y;
            dv[k]    = v1.x - v1.y;
        }

#pragma unroll
        for (int h = 0; h < RPT; h++) {
            const int kn = (h + 2) % 3;   // slot for the new (bottom) row
            const int km = (h + 1) % 3;   // slot holding the center row
            int pr = row_base + h + 2;
            float2 v0 = buf[pr][col], v1 = buf[pr][col + 1], v2 = buf[pr][col + 2];
            rs_x[kn]  = v0.x + v1.x + v2.x;
            rs_y[kn]  = v0.y + v1.y + v2.y;
            rs_q[kn]  = v0.x * v0.x + v0.y * v0.y + v1.x * v1.x + v1.y * v1.y
                      + v2.x * v2.x + v2.y * v2.y;
            rs_xy[kn] = v0.x * v0.y + v1.x * v1.y + v2.x * v2.y;
            dv[kn]    = v1.x - v1.y;

            float Sx  = rs_x[0]  + rs_x[1]  + rs_x[2];
            float Sy  = rs_y[0]  + rs_y[1]  + rs_y[2];
            float Sq  = rs_q[0]  + rs_q[1]  + rs_q[2];   // Sxx + Syy
            float Sxy = rs_xy[0] + rs_xy[1] + rs_xy[2];

            // Scaled-through SSIM (exact rearrangement; uses C2 = 9*C1):
            //   ns = 0.5 - (P*Q)/(R*T)/18
            float t = Sx * Sy;
            float P = fmaf(2.0f, t, KC);
            float Q = fmaf(18.0f, Sxy, fmaf(-2.0f, t, KC9));
            float R = fmaf(Sx, Sx, fmaf(Sy, Sy, KC));
            float T = Sq + (KC - (Sx + Sy));
            float ratio = __fdividef(P * Q, R * T);
            float ns = fmaf(ratio, -(1.0f / 18.0f), 0.5f);
            ns = fminf(fmaxf(ns, 0.0f), 1.0f);

            acc[h] = fmaf(0.425f, ns, fmaf(0.15f, fabsf(dv[km]), acc[h]));
        }
    }

    // Combine and write (coalesced per warp-row)
    float* __restrict__ ob = out + (size_t)b * Hd * Wd;
#pragma unroll
    for (int h = 0; h < RPT; h++) {
        int gr = h0 + row_base + h;
        ob[gr * Wd + w0 + col] = acc[h] * (1.0f / 3.0f);
    }
}

extern "C" void kernel_launch(void* const* d_in, const int* in_sizes, int n_in,
                              void* d_out, int out_size) {
    const float* X = (const float*)d_in[0];   // output
    const float* Y = (const float*)d_in[1];   // target
    float* O = (float*)d_out;

    dim3 grid(Wd / TW, Hd / TH, Bn);   // 5 x 24 x 32
    dim3 block(256);
    recon_loss_kernel<<<grid, block>>>(X, Y, O);
}

// round 14
// speedup vs baseline: 1.1832x; 1.0258x over previous
#include <cuda_runtime.h>

// Problem constants
#define Bn 32
#define Cc 3
#define Hd 384
#define Wd 640

// Tiling
#define TW 128      // output cols per block
#define TH 16       // output rows per block
#define PW 130      // padded cols (TW + 2)
#define PWs 132     // smem row stride (in float2)
#define PH 18       // padded rows (TH + 2)
#define RPT 8       // rows per thread (TH / 2)

typedef unsigned long long u64t;

__device__ __forceinline__ int reflect1(int i, int n) {
    // jnp.pad mode='reflect', pad=1: -1 -> 1, n -> n-2
    if (i < 0) i = -i;
    if (i >= n) i = 2 * n - 2 - i;
    return i;
}

__device__ __forceinline__ void cp4(unsigned dst, const float* src) {
    asm volatile("cp.async.ca.shared.global [%0], [%1], 4;\n"
                 :: "r"(dst), "l"(src));
}

// ---- packed f32x2 helpers (FFMA2/FADD2/FMUL2 — PTX-only on sm_103a) ----
__device__ __forceinline__ u64t f2p(float2 v) {
    u64t r; asm("mov.b64 %0, {%1, %2};" : "=l"(r) : "f"(v.x), "f"(v.y)); return r;
}
__device__ __forceinline__ float2 p2f(u64t p) {
    float2 v; asm("mov.b64 {%0, %1}, %2;" : "=f"(v.x), "=f"(v.y) : "l"(p)); return v;
}
__device__ __forceinline__ u64t addx2(u64t a, u64t b) {
    u64t r; asm("add.rn.f32x2 %0, %1, %2;" : "=l"(r) : "l"(a), "l"(b)); return r;
}
__device__ __forceinline__ u64t mulx2(u64t a, u64t b) {
    u64t r; asm("mul.rn.f32x2 %0, %1, %2;" : "=l"(r) : "l"(a), "l"(b)); return r;
}
__device__ __forceinline__ u64t fmax2(u64t a, u64t b, u64t c) {
    u64t r; asm("fma.rn.f32x2 %0, %1, %2, %3;" : "=l"(r) : "l"(a), "l"(b), "l"(c)); return r;
}

__global__ __launch_bounds__(256, 3)
void recon_loss_kernel(const float* __restrict__ X,
                       const float* __restrict__ Y,
                       float* __restrict__ out) {
    // Ping-pong interleaved (x, y) tiles: LDS.64 reads, cp.async fills.
    __shared__ float2 s[2][PH][PWs];

    const int w0 = blockIdx.x * TW;
    const int h0 = blockIdx.y * TH;
    const int b  = blockIdx.z;
    const int tid = threadIdx.x;
    const int col = tid & (TW - 1);        // 0..127
    const int row_base = (tid >> 7) * RPT; // 0 or 8

    // ---- load geometry: computed ONCE, reused for all 3 channels ----
    const int i0 = tid >> 7;                       // 0 or 1
    const int jm = tid & 127;                      // padded col 0..127
    const int gcm = reflect1(w0 - 1 + jm, Wd);     // reflected global col
    const int rb  = h0 - 1 + i0;                   // base padded-row
    // Tail: 36 threads cover padded cols 128,129 for all 18 rows.
    const bool tail = tid < 36;
    const int ti  = tid >> 1;                      // 0..17
    const int tj  = 128 + (tid & 1);
    const int tg  = reflect1(h0 - 1 + ti, Hd) * Wd + reflect1(w0 - 1 + tj, Wd);

    const float KC  = 526.7025f;    // 81*C1 == 9*C2
    const float KC9 = 4740.3225f;   // 81*C2

    float acc[RPT];
#pragma unroll
    for (int i = 0; i < RPT; i++) acc[i] = 0.0f;

    // Async-load channel cc into buffer cc&1
    auto issue_loads = [&](int cc) {
        const float* __restrict__ xb = X + (size_t)(b * Cc + cc) * (Hd * Wd);
        const float* __restrict__ yb = Y + (size_t)(b * Cc + cc) * (Hd * Wd);
        float2 (*buf)[PWs] = s[cc & 1];
#pragma unroll
        for (int k = 0; k < 9; k++) {
            int gr = reflect1(rb + 2 * k, Hd);
            int g  = gr * Wd + gcm;
            unsigned dst = (unsigned)__cvta_generic_to_shared(&buf[i0 + 2 * k][jm]);
            cp4(dst,     xb + g);
            cp4(dst + 4, yb + g);
        }
        if (tail) {
            unsigned dst = (unsigned)__cvta_generic_to_shared(&buf[ti][tj]);
            cp4(dst,     xb + tg);
            cp4(dst + 4, yb + tg);
        }
        asm volatile("cp.async.commit_group;\n" ::: "memory");
    };

    issue_loads(0);

    for (int c = 0; c < Cc; c++) {
        // Retire group filling buffer c; barrier publishes it CTA-wide and
        // orders compute on the other buffer before we refill it.
        asm volatile("cp.async.wait_group 0;\n" ::: "memory");
        __syncthreads();
        if (c + 1 < Cc) issue_loads(c + 1);   // overlaps with compute below

        float2 (*buf)[PWs] = s[c & 1];

        // Rolling horizontal row-sums (ring of 3):
        //   rs_s  = packed (sum x, sum y)
        //   rs_q  = sum (x^2 + y^2)      rs_xy = sum x*y     dv = x_c - y_c
        u64t  rs_s[3];
        float rs_q[3], rs_xy[3], dv[3];

#pragma unroll
        for (int k = 0; k < 2; k++) {
            int pr = row_base + k;
            float2 v0 = buf[pr][col], v1 = buf[pr][col + 1], v2 = buf[pr][col + 2];
            u64t p0 = f2p(v0), p1 = f2p(v1), p2 = f2p(v2);
            rs_s[k] = addx2(addx2(p0, p1), p2);
            float2 q = p2f(fmax2(p2, p2, fmax2(p1, p1, mulx2(p0, p0))));
            rs_q[k]  = q.x + q.y;
            rs_xy[k] = fmaf(v0.x, v0.y, fmaf(v1.x, v1.y, v2.x * v2.y));
            dv[k]    = v1.x - v1.y;
        }

#pragma unroll
        for (int h = 0; h < RPT; h++) {
            const int kn = (h + 2) % 3;   // slot for the new (bottom) row
            const int km = (h + 1) % 3;   // slot holding the center row
            int pr = row_base + h + 2;
            float2 v0 = buf[pr][col], v1 = buf[pr][col + 1], v2 = buf[pr][col + 2];
            u64t p0 = f2p(v0), p1 = f2p(v1), p2 = f2p(v2);
            rs_s[kn] = addx2(addx2(p0, p1), p2);
            float2 q = p2f(fmax2(p2, p2, fmax2(p1, p1, mulx2(p0, p0))));
            rs_q[kn]  = q.x + q.y;
            rs_xy[kn] = fmaf(v0.x, v0.y, fmaf(v1.x, v1.y, v2.x * v2.y));
            dv[kn]    = v1.x - v1.y;

            // 3x3 window sums
            float2 S = p2f(addx2(addx2(rs_s[0], rs_s[1]), rs_s[2]));
            float Sx  = S.x;
            float Sy  = S.y;
            float Sq  = rs_q[0]  + rs_q[1]  + rs_q[2];   // Sxx + Syy
            float Sxy = rs_xy[0] + rs_xy[1] + rs_xy[2];

            // Scaled-through SSIM (exact rearrangement; uses C2 = 9*C1):
            //   ns = 0.5 - (P*Q)/(R*T)/18
            float t = Sx * Sy;
            float P = fmaf(2.0f, t, KC);
            float Q = fmaf(18.0f, Sxy, fmaf(-2.0f, t, KC9));
            float R = fmaf(Sx, Sx, fmaf(Sy, Sy, KC));
            float T = Sq + (KC - (Sx + Sy));
            float ratio = __fdividef(P * Q, R * T);
            float ns = fmaf(ratio, -(1.0f / 18.0f), 0.5f);
            ns = fminf(fmaxf(ns, 0.0f), 1.0f);

            acc[h] = fmaf(0.425f, ns, fmaf(0.15f, fabsf(dv[km]), acc[h]));
        }
    }

    // Combine and write (coalesced per warp-row)
    float* __restrict__ ob = out + (size_t)b * Hd * Wd;
#pragma unroll
    for (int h = 0; h < RPT; h++) {
        int gr = h0 + row_base + h;
        ob[gr * Wd + w0 + col] = acc[h] * (1.0f / 3.0f);
    }
}

extern "C" void kernel_launch(void* const* d_in, const int* in_sizes, int n_in,
                              void* d_out, int out_size) {
    const float* X = (const float*)d_in[0];   // output
    const float* Y = (const float*)d_in[1];   // target
    float* O = (float*)d_out;

    dim3 grid(Wd / TW, Hd / TH, Bn);   // 5 x 24 x 32
    dim3 block(256);
    recon_loss_kernel<<<grid, block>>>(X, Y, O);
}